// round 1
// baseline (speedup 1.0000x reference)
#include <cuda_runtime.h>
#include <math.h>

#define D_MODEL 1024
#define SEQ     2048
#define BATCH   4
#define ROWS    (BATCH*SEQ)   // 8192
#define DS      16
#define DFF     4096
#define NHEADS  8
#define HDIM    128

// ---------------- scratch (static device memory: allowed) ----------------
__device__ float g_xn  [ROWS*D_MODEL];
__device__ float g_xn1 [ROWS*D_MODEL];
__device__ float g_gate[ROWS*D_MODEL];
__device__ float g_mamba[ROWS*D_MODEL];
__device__ float g_q   [ROWS*D_MODEL];
__device__ float g_k   [ROWS*D_MODEL];
__device__ float g_v   [ROWS*D_MODEL];
__device__ float g_ctx [ROWS*D_MODEL];
__device__ float g_x2  [ROWS*D_MODEL];
__device__ float g_xn2 [ROWS*D_MODEL];
__device__ float g_tout[ROWS*D_MODEL];
__device__ float g_y   [ROWS*D_MODEL];
__device__ float g_ffn1[ROWS*DFF];
__device__ float g_delta[ROWS*DS];
__device__ float g_bt  [ROWS*DS];
__device__ float g_h   [ROWS*DS];

__device__ __forceinline__ float tanh_fast(float x){
    float y; asm("tanh.approx.f32 %0, %1;" : "=f"(y) : "f"(x)); return y;
}

// ---------------- LayerNorm (optionally dual-output) ----------------
__global__ void __launch_bounds__(256) ln_kernel(
    const float* __restrict__ x,
    const float* __restrict__ g0, const float* __restrict__ b0, float* __restrict__ out0,
    const float* __restrict__ g1, const float* __restrict__ b1, float* __restrict__ out1)
{
    __shared__ float red[64];
    const int row = blockIdx.x;
    const int tid = threadIdx.x;
    const float4 v = ((const float4*)(x + (size_t)row*D_MODEL))[tid];
    float s  = v.x+v.y+v.z+v.w;
    float sq = v.x*v.x+v.y*v.y+v.z*v.z+v.w*v.w;
    #pragma unroll
    for (int o=16;o;o>>=1){ s += __shfl_xor_sync(0xffffffffu,s,o); sq += __shfl_xor_sync(0xffffffffu,sq,o); }
    if ((tid&31)==0){ red[tid>>5]=s; red[(tid>>5)+8]=sq; }
    __syncthreads();
    if (tid<32){
        float ss=(tid<8)?red[tid]:0.f, qq=(tid<8)?red[tid+8]:0.f;
        #pragma unroll
        for (int o=4;o;o>>=1){ ss += __shfl_xor_sync(0xffffffffu,ss,o); qq += __shfl_xor_sync(0xffffffffu,qq,o); }
        if (tid==0){ red[32]=ss; red[33]=qq; }
    }
    __syncthreads();
    const float mean = red[32]*(1.f/D_MODEL);
    const float var  = red[33]*(1.f/D_MODEL) - mean*mean;
    const float inv  = rsqrtf(var + 1e-5f);
    {
        const float4 g = ((const float4*)g0)[tid];
        const float4 b = ((const float4*)b0)[tid];
        float4 o0;
        o0.x = (v.x-mean)*inv*g.x + b.x;
        o0.y = (v.y-mean)*inv*g.y + b.y;
        o0.z = (v.z-mean)*inv*g.z + b.z;
        o0.w = (v.w-mean)*inv*g.w + b.w;
        ((float4*)(out0 + (size_t)row*D_MODEL))[tid] = o0;
    }
    if (out1){
        const float4 g = ((const float4*)g1)[tid];
        const float4 b = ((const float4*)b1)[tid];
        float4 o1;
        o1.x = (v.x-mean)*inv*g.x + b.x;
        o1.y = (v.y-mean)*inv*g.y + b.y;
        o1.z = (v.z-mean)*inv*g.z + b.z;
        o1.w = (v.w-mean)*inv*g.w + b.w;
        ((float4*)(out1 + (size_t)row*D_MODEL))[tid] = o1;
    }
}

// ---------------- delta / Bt (K=1024, N=16 each) ----------------
__global__ void __launch_bounds__(256) delta_bt_kernel(
    const float* __restrict__ xn,
    const float* __restrict__ Wd, const float* __restrict__ bd,
    const float* __restrict__ Wi, const float* __restrict__ bi,
    float* __restrict__ delta, float* __restrict__ bt)
{
    __shared__ float xs[D_MODEL];
    __shared__ float red[256];
    const int row = blockIdx.x, tid = threadIdx.x;
    ((float4*)xs)[tid] = ((const float4*)(xn + (size_t)row*D_MODEL))[tid];
    __syncthreads();
    const int c = tid & 15;
    const int which = (tid>>4)&1;
    const int grp = tid>>5;              // 0..7
    const float* W = which ? Wi : Wd;
    float acc = 0.f;
    const int k0 = grp*128;
    #pragma unroll 8
    for (int k=0;k<128;k++) acc += xs[k0+k]*W[(size_t)(k0+k)*16 + c];
    red[tid]=acc; __syncthreads();
    if (tid<32){
        float sacc=0.f;
        #pragma unroll
        for (int g=0;g<8;g++) sacc += red[g*32+tid];
        if (tid<16) delta[(size_t)row*16+tid] = 1.f/(1.f+__expf(-(sacc+bd[tid])));
        else        bt   [(size_t)row*16+tid-16] = sacc + bi[tid-16];
    }
}

// ---------------- sequential mamba scan (1 warp per batch) ----------------
__global__ void __launch_bounds__(32) scan_kernel(
    const float* __restrict__ delta, const float* __restrict__ bt,
    const float* __restrict__ A, float* __restrict__ h_all)
{
    __shared__ float ds[128*16], bs[128*16];
    const int b = blockIdx.x, lane = threadIdx.x;
    const int j = lane & 15;
    float Acol[16];
    #pragma unroll
    for (int i=0;i<16;i++) Acol[i] = A[i*16 + j];
    float h = 0.f;
    const float* dp = delta + (size_t)b*SEQ*16;
    const float* bp = bt    + (size_t)b*SEQ*16;
    float* hp = h_all + (size_t)b*SEQ*16;
    for (int chunk=0; chunk<SEQ; chunk+=128){
        const float4* s0 = (const float4*)(dp + (size_t)chunk*16);
        const float4* s1 = (const float4*)(bp + (size_t)chunk*16);
        for (int i=lane;i<512;i+=32){ ((float4*)ds)[i]=s0[i]; ((float4*)bs)[i]=s1[i]; }
        __syncwarp();
        #pragma unroll 4
        for (int t=0;t<128;t++){
            const float d = ds[t*16+j];
            const float bv = bs[t*16+j];
            const float v = h*d;
            float a0 = bv, a1 = 0.f;
            #pragma unroll
            for (int i=0;i<16;i+=2){
                a0 += __shfl_sync(0xffffffffu, v, i,   16)*Acol[i];
                a1 += __shfl_sync(0xffffffffu, v, i+1, 16)*Acol[i+1];
            }
            h = tanh_fast(a0+a1);
            if (lane<16) hp[(size_t)(chunk+t)*16 + j] = h;
        }
        __syncwarp();
    }
}

// ---------------- mamba_out = (h @ C) * gate + x ----------------
__global__ void __launch_bounds__(256) mamba_out_kernel(
    const float* __restrict__ h_all, const float* __restrict__ Cm,
    const float* __restrict__ gate, const float* __restrict__ x,
    float* __restrict__ out)
{
    __shared__ float hs[16];
    const int row = blockIdx.x, tid = threadIdx.x;
    if (tid<16) hs[tid] = h_all[(size_t)row*16+tid];
    __syncthreads();
    const size_t base = (size_t)row*D_MODEL;
    #pragma unroll
    for (int kk=0; kk<4; kk++){
        const int c = tid + kk*256;
        float acc = 0.f;
        #pragma unroll
        for (int i=0;i<16;i++) acc += hs[i]*Cm[(size_t)i*D_MODEL + c];
        out[base+c] = acc*gate[base+c] + x[base+c];
    }
}

// ---------------- generic SGEMM: C = act(A@B + bias) (+res) (+Cold) ----------------
// A: MxK row-major, B: KxN row-major. Tiles 128x128xk8, 256 threads, 8x8/thread.
template<int ACT, bool ACC>
__global__ void __launch_bounds__(256) sgemm_kernel(
    const float* __restrict__ A, const float* __restrict__ B,
    const float* __restrict__ bias, const float* __restrict__ res,
    float* __restrict__ C, int M, int N, int K)
{
    __shared__ float As[2][8][128];
    __shared__ float Bs[2][8][128];
    const int tid  = threadIdx.x;
    const int row0 = blockIdx.y*128;
    const int col0 = blockIdx.x*128;

    const int arow = tid>>1, acol = (tid&1)<<2;
    const int brow = tid>>5, bcol = (tid&31)<<2;
    const float* Ap = A + (size_t)(row0+arow)*K + acol;
    const float* Bp = B + (size_t)brow*N + col0 + bcol;
    const int tx = tid & 15, ty = tid>>4;

    float acc[8][8];
    #pragma unroll
    for (int i=0;i<8;i++){
        #pragma unroll
        for (int j=0;j<8;j++) acc[i][j]=0.f;
    }

    float4 av = *(const float4*)Ap;
    float4 bv = *(const float4*)Bp;
    As[0][acol+0][arow]=av.x; As[0][acol+1][arow]=av.y;
    As[0][acol+2][arow]=av.z; As[0][acol+3][arow]=av.w;
    *(float4*)&Bs[0][brow][bcol] = bv;
    __syncthreads();

    const int nk = K>>3;
    for (int kt=0; kt<nk; ++kt){
        const int cur = kt & 1;
        if (kt+1 < nk){
            av = *(const float4*)(Ap + (size_t)(kt+1)*8);
            bv = *(const float4*)(Bp + (size_t)(kt+1)*8*N);
        }
        #pragma unroll
        for (int kk=0;kk<8;kk++){
            float a[8], b[8];
            *(float4*)&a[0] = *(const float4*)&As[cur][kk][ty*8];
            *(float4*)&a[4] = *(const float4*)&As[cur][kk][ty*8+4];
            *(float4*)&b[0] = *(const float4*)&Bs[cur][kk][tx*8];
            *(float4*)&b[4] = *(const float4*)&Bs[cur][kk][tx*8+4];
            #pragma unroll
            for (int i=0;i<8;i++){
                #pragma unroll
                for (int j=0;j<8;j++) acc[i][j] += a[i]*b[j];
            }
        }
        if (kt+1 < nk){
            const int nxt = cur^1;
            As[nxt][acol+0][arow]=av.x; As[nxt][acol+1][arow]=av.y;
            As[nxt][acol+2][arow]=av.z; As[nxt][acol+3][arow]=av.w;
            *(float4*)&Bs[nxt][brow][bcol] = bv;
            __syncthreads();
        }
    }

    float bs_[8];
    #pragma unroll
    for (int j=0;j<8;j++) bs_[j] = bias ? bias[col0 + tx*8 + j] : 0.f;
    #pragma unroll
    for (int i=0;i<8;i++){
        const size_t off = (size_t)(row0 + ty*8 + i)*N + col0 + tx*8;
        float v[8];
        #pragma unroll
        for (int j=0;j<8;j++){
            float t = acc[i][j] + bs_[j];
            if (ACT==1) t = 1.f/(1.f+__expf(-t));
            else if (ACT==2) t = fmaxf(t, 0.f);
            v[j] = t;
        }
        if (res){
            #pragma unroll
            for (int j=0;j<8;j++) v[j] += res[off+j];
        }
        if (ACC){
            #pragma unroll
            for (int j=0;j<8;j++) v[j] += C[off+j];
        }
        *(float4*)&C[off]   = make_float4(v[0],v[1],v[2],v[3]);
        *(float4*)&C[off+4] = make_float4(v[4],v[5],v[6],v[7]);
    }
}

// ---------------- fp32 flash attention ----------------
// grid: (SEQ/64, B*H), block 256, dyn smem ~82KB
__global__ void __launch_bounds__(256) attn_kernel(
    const float* __restrict__ Q, const float* __restrict__ K,
    const float* __restrict__ V, float* __restrict__ O)
{
    extern __shared__ float sm[];
    float* Qs   = sm;                  // 64*128
    float* KVs  = sm + 64*128;         // 64*128
    float* Ss   = sm + 2*64*128;       // 64*64
    float* mrow = Ss + 64*64;          // 64
    float* lrow = mrow + 64;           // 64
    float* arow = lrow + 64;           // 64

    const int tid = threadIdx.x;
    const int q0  = blockIdx.x*64;
    const int b   = blockIdx.y>>3;
    const int h   = blockIdx.y&7;
    const float* Qb = Q + ((size_t)b*SEQ + q0)*D_MODEL + h*HDIM;
    const float* Kb = K + (size_t)b*SEQ*D_MODEL + h*HDIM;
    const float* Vb = V + (size_t)b*SEQ*D_MODEL + h*HDIM;
    const float scale = 0.08838834764831845f; // 1/sqrt(128)

    for (int i=tid;i<64*32;i+=256){
        const int r=i>>5, c=(i&31)<<2;
        float4 t = *(const float4*)(Qb + (size_t)r*D_MODEL + c);
        t.x*=scale; t.y*=scale; t.z*=scale; t.w*=scale;
        *(float4*)&Qs[r*128+c] = t;
    }
    if (tid<64){ mrow[tid]=-1e30f; lrow[tid]=0.f; }

    const int str = tid>>4, stc = tid&15;
    float o[4][8];
    #pragma unroll
    for (int i=0;i<4;i++){
        #pragma unroll
        for (int j=0;j<8;j++) o[i][j]=0.f;
    }
    __syncthreads();

    for (int kt=0; kt<SEQ; kt+=64){
        for (int i=tid;i<64*32;i+=256){
            const int r=i>>5, c=(i&31)<<2;
            *(float4*)&KVs[r*128+c] = *(const float4*)(Kb + (size_t)(kt+r)*D_MODEL + c);
        }
        __syncthreads();

        float s[4][4];
        #pragma unroll
        for (int i=0;i<4;i++){
            #pragma unroll
            for (int j=0;j<4;j++) s[i][j]=0.f;
        }
        for (int d0=0; d0<128; d0+=4){
            float4 qv[4], kv[4];
            #pragma unroll
            for (int i=0;i<4;i++) qv[i] = *(const float4*)&Qs[(str*4+i)*128 + d0];
            #pragma unroll
            for (int j=0;j<4;j++) kv[j] = *(const float4*)&KVs[(stc*4+j)*128 + d0];
            #pragma unroll
            for (int i=0;i<4;i++){
                #pragma unroll
                for (int j=0;j<4;j++)
                    s[i][j] += qv[i].x*kv[j].x + qv[i].y*kv[j].y + qv[i].z*kv[j].z + qv[i].w*kv[j].w;
            }
        }

        #pragma unroll
        for (int i=0;i<4;i++){
            const int r = str*4+i;
            float mx = fmaxf(fmaxf(s[i][0],s[i][1]), fmaxf(s[i][2],s[i][3]));
            #pragma unroll
            for (int off=8; off; off>>=1) mx = fmaxf(mx, __shfl_xor_sync(0xffffffffu,mx,off));
            const float mold = mrow[r];
            const float mnew = fmaxf(mold, mx);
            const float p0=__expf(s[i][0]-mnew), p1=__expf(s[i][1]-mnew);
            const float p2=__expf(s[i][2]-mnew), p3=__expf(s[i][3]-mnew);
            float sum = p0+p1+p2+p3;
            #pragma unroll
            for (int off=8; off; off>>=1) sum += __shfl_xor_sync(0xffffffffu,sum,off);
            if (stc==0){
                const float al = __expf(mold-mnew);
                mrow[r]=mnew; lrow[r]=lrow[r]*al+sum; arow[r]=al;
            }
            *(float4*)&Ss[r*64 + stc*4] = make_float4(p0,p1,p2,p3);
        }
        __syncthreads();

        for (int i=tid;i<64*32;i+=256){
            const int r=i>>5, c=(i&31)<<2;
            *(float4*)&KVs[r*128+c] = *(const float4*)(Vb + (size_t)(kt+r)*D_MODEL + c);
        }
        __syncthreads();

        #pragma unroll
        for (int i=0;i<4;i++){
            const float al = arow[str*4+i];
            #pragma unroll
            for (int j=0;j<8;j++) o[i][j] *= al;
        }
        for (int kk=0; kk<64; kk+=4){
            float pr[4][4];
            #pragma unroll
            for (int i=0;i<4;i++){
                const float4 p = *(const float4*)&Ss[(str*4+i)*64 + kk];
                pr[i][0]=p.x; pr[i][1]=p.y; pr[i][2]=p.z; pr[i][3]=p.w;
            }
            #pragma unroll
            for (int dd=0; dd<4; dd++){
                float vv[8];
                *(float4*)&vv[0] = *(const float4*)&KVs[(kk+dd)*128 + stc*8];
                *(float4*)&vv[4] = *(const float4*)&KVs[(kk+dd)*128 + stc*8 + 4];
                #pragma unroll
                for (int i=0;i<4;i++){
                    #pragma unroll
                    for (int j=0;j<8;j++) o[i][j] += pr[i][dd]*vv[j];
                }
            }
        }
        __syncthreads();
    }

    float* Ob = O + ((size_t)b*SEQ + q0)*D_MODEL + h*HDIM;
    #pragma unroll
    for (int i=0;i<4;i++){
        const int r = str*4+i;
        const float inv = 1.f/lrow[r];
        *(float4*)(Ob + (size_t)r*D_MODEL + stc*8)     = make_float4(o[i][0]*inv,o[i][1]*inv,o[i][2]*inv,o[i][3]*inv);
        *(float4*)(Ob + (size_t)r*D_MODEL + stc*8 + 4) = make_float4(o[i][4]*inv,o[i][5]*inv,o[i][6]*inv,o[i][7]*inv);
    }
}

// ---------------- launch ----------------
extern "C" void kernel_launch(void* const* d_in, const int* in_sizes, int n_in,
                              void* d_out, int out_size)
{
    const float* x      = (const float*)d_in[0];
    const float* ln_g   = (const float*)d_in[1];
    const float* ln_b   = (const float*)d_in[2];
    const float* Wdelta = (const float*)d_in[3];
    const float* bdelta = (const float*)d_in[4];
    const float* Win    = (const float*)d_in[5];
    const float* b_in   = (const float*)d_in[6];
    const float* Wgate  = (const float*)d_in[7];
    const float* bgate  = (const float*)d_in[8];
    const float* Amat   = (const float*)d_in[9];
    const float* Cmat   = (const float*)d_in[10];
    const float* ln1_g  = (const float*)d_in[11];
    const float* ln1_b  = (const float*)d_in[12];
    const float* Wq     = (const float*)d_in[13];
    const float* bq     = (const float*)d_in[14];
    const float* Wk     = (const float*)d_in[15];
    const float* bk     = (const float*)d_in[16];
    const float* Wv     = (const float*)d_in[17];
    const float* bv     = (const float*)d_in[18];
    const float* Wo     = (const float*)d_in[19];
    const float* bo     = (const float*)d_in[20];
    const float* ln2_g  = (const float*)d_in[21];
    const float* ln2_b  = (const float*)d_in[22];
    const float* W1     = (const float*)d_in[23];
    const float* b1     = (const float*)d_in[24];
    const float* W2     = (const float*)d_in[25];
    const float* b2     = (const float*)d_in[26];
    const float* Wf     = (const float*)d_in[27];
    const float* bf     = (const float*)d_in[28];
    const float* lnf_g  = (const float*)d_in[29];
    const float* lnf_b  = (const float*)d_in[30];

    float *xn,*xn1,*gate,*mamba,*q,*k,*v,*ctx,*x2,*xn2,*tout,*y,*ffn1,*delta,*bt,*h;
    cudaGetSymbolAddress((void**)&xn,   g_xn);
    cudaGetSymbolAddress((void**)&xn1,  g_xn1);
    cudaGetSymbolAddress((void**)&gate, g_gate);
    cudaGetSymbolAddress((void**)&mamba,g_mamba);
    cudaGetSymbolAddress((void**)&q,    g_q);
    cudaGetSymbolAddress((void**)&k,    g_k);
    cudaGetSymbolAddress((void**)&v,    g_v);
    cudaGetSymbolAddress((void**)&ctx,  g_ctx);
    cudaGetSymbolAddress((void**)&x2,   g_x2);
    cudaGetSymbolAddress((void**)&xn2,  g_xn2);
    cudaGetSymbolAddress((void**)&tout, g_tout);
    cudaGetSymbolAddress((void**)&y,    g_y);
    cudaGetSymbolAddress((void**)&ffn1, g_ffn1);
    cudaGetSymbolAddress((void**)&delta,g_delta);
    cudaGetSymbolAddress((void**)&bt,   g_bt);
    cudaGetSymbolAddress((void**)&h,    g_h);

    const dim3 gD(D_MODEL/128, ROWS/128);   // N=1024
    const dim3 gF(DFF/128,     ROWS/128);   // N=4096

    // Mamba branch prep
    ln_kernel<<<ROWS,256>>>(x, ln_g, ln_b, xn, ln1_g, ln1_b, xn1);
    delta_bt_kernel<<<ROWS,256>>>(xn, Wdelta, bdelta, Win, b_in, delta, bt);
    scan_kernel<<<BATCH,32>>>(delta, bt, Amat, h);
    sgemm_kernel<1,false><<<gD,256>>>(xn, Wgate, bgate, nullptr, gate, ROWS, D_MODEL, D_MODEL);
    mamba_out_kernel<<<ROWS,256>>>(h, Cmat, gate, x, mamba);

    // Transformer branch
    sgemm_kernel<0,false><<<gD,256>>>(xn1, Wq, bq, nullptr, q, ROWS, D_MODEL, D_MODEL);
    sgemm_kernel<0,false><<<gD,256>>>(xn1, Wk, bk, nullptr, k, ROWS, D_MODEL, D_MODEL);
    sgemm_kernel<0,false><<<gD,256>>>(xn1, Wv, bv, nullptr, v, ROWS, D_MODEL, D_MODEL);

    const size_t attn_smem = (size_t)(2*64*128 + 64*64 + 3*64)*sizeof(float);
    cudaFuncSetAttribute(attn_kernel, cudaFuncAttributeMaxDynamicSharedMemorySize, (int)attn_smem);
    attn_kernel<<<dim3(SEQ/64, BATCH*NHEADS), 256, attn_smem>>>(q, k, v, ctx);

    sgemm_kernel<0,false><<<gD,256>>>(ctx, Wo, bo, x, x2, ROWS, D_MODEL, D_MODEL);
    ln_kernel<<<ROWS,256>>>(x2, ln2_g, ln2_b, xn2, nullptr, nullptr, nullptr);
    sgemm_kernel<2,false><<<gF,256>>>(xn2, W1, b1, nullptr, ffn1, ROWS, DFF, D_MODEL);
    sgemm_kernel<0,false><<<gD,256>>>(ffn1, W2, b2, x2, tout, ROWS, D_MODEL, DFF);

    // Fusion: y = mamba @ Wf[:D] + bf ; y += tout @ Wf[D:]
    sgemm_kernel<0,false><<<gD,256>>>(mamba, Wf, bf, nullptr, y, ROWS, D_MODEL, D_MODEL);
    sgemm_kernel<0,true ><<<gD,256>>>(tout, Wf + (size_t)D_MODEL*D_MODEL, nullptr, nullptr, y, ROWS, D_MODEL, D_MODEL);

    // Final LN -> output
    ln_kernel<<<ROWS,256>>>(y, lnf_g, lnf_b, (float*)d_out, nullptr, nullptr, nullptr);
}